// round 6
// baseline (speedup 1.0000x reference)
#include <cuda_runtime.h>
#include <math.h>

// Tropical (max-plus) depthwise 5x5 conv, stride 1, pad 2 (-inf), dilation 1.
// x: [8,32,224,224] f32, kernel: [32,1,5,5] f32, out same shape.
// out[b,c,h,w] = max_{i,j} ( x_pad[b,c,h+i,w+j] + kflip[c,i,j] ),
// kflip[c,i,j] = kernel[c,0,4-i,4-j].
//
// R5: packed f32x2 adds (add.rn.f32x2), paired along the j (horizontal tap)
// axis so the packed weight operand (w[i,j], w[i,j+1]) is built once at setup
// (weight register count unchanged at 25). Per (input row, output row, q):
//   2 x FADD2 (taps j=0,1 and j=2,3) + 1 x FADD (tap j=4) + 5 x FMNMX
// vs the previous 5 x FADD + 5 x FMNMX  -> 20% fewer issued instructions.
// Even-phase v pairs alias LDG.128 register pairs; 3 odd-phase pairs per row
// are packed explicitly.
// Tile: 4-wide x 8-tall per thread, cyclic 5-row accumulator window,
// 2 aligned float4 loads per input row, predicated float2 stores.
// Plane layout: 57 col-groups x 28 row-groups, 256 planes -> 1596 blocks.

#define HW 224
#define NEG_INF (-INFINITY)

typedef unsigned long long u64;

__device__ __forceinline__ u64 pack2(float a, float b) {
    u64 r;
    asm("mov.b64 %0, {%1, %2};" : "=l"(r) : "f"(a), "f"(b));
    return r;
}

// acc = max(acc, lo(vp + wp)); acc = max(acc, hi(vp + wp))
// One packed FADD2 produces two tap candidates for the SAME output element.
__device__ __forceinline__ void add2_max(float& acc, u64 vp, u64 wp) {
    float lo, hi;
    asm("{\n\t"
        ".reg .b64 t;\n\t"
        "add.rn.f32x2 t, %2, %3;\n\t"
        "mov.b64 {%0, %1}, t;\n\t"
        "}"
        : "=f"(lo), "=f"(hi) : "l"(vp), "l"(wp));
    acc = fmaxf(acc, lo);
    acc = fmaxf(acc, hi);
}

__global__ __launch_bounds__(256, 4) void tropical_conv_kernel(
    const float* __restrict__ x,
    const float* __restrict__ w,
    float* __restrict__ out)
{
    const int gid   = blockIdx.x * blockDim.x + threadIdx.x;
    const int plane = gid / 1596;           // b*32 + c, 0..255
    const int rem   = gid - plane * 1596;
    const int rg    = rem / 57;             // row group 0..27 (output rows rg*8..rg*8+7)
    const int tx    = rem - rg * 57;        // col group 0..56
    const int c     = plane & 31;

    // Flipped weights: packed pairs (j=0,1) and (j=2,3) + scalar j=4 per row i.
    u64   wp01[5], wp23[5];
    float w4[5];
#pragma unroll
    for (int i = 0; i < 5; i++) {
        const float w0 = __ldg(&w[c * 25 + (4 - i) * 5 + 4]);
        const float w1 = __ldg(&w[c * 25 + (4 - i) * 5 + 3]);
        const float w2 = __ldg(&w[c * 25 + (4 - i) * 5 + 2]);
        const float w3 = __ldg(&w[c * 25 + (4 - i) * 5 + 1]);
        const float wv4 = __ldg(&w[c * 25 + (4 - i) * 5 + 0]);
        wp01[i] = pack2(w0, w1);
        wp23[i] = pack2(w2, w3);
        w4[i]   = wv4;
    }

    const float* xp = x + (size_t)plane * (HW * HW);
    float* op_base  = out + (size_t)plane * (HW * HW) + (rg * 8) * HW + (tx * 4 - 2);

    const int colL = tx * 4 - 4;            // left aligned quad: cols colL..colL+3
    const int row0 = rg * 8 - 2;            // first input row of the 12-row window

    const bool ldL = (tx > 0);
    const bool ldR = (tx < 56);

    float acc[5][4];                        // cyclic window of 5 active output rows

#pragma unroll
    for (int r = 0; r < 12; r++) {
        const int gr = row0 + r;
        const bool rowok = (gr >= 0) && (gr < HW);

        float v[8];                         // input cols colL .. colL+7
        if (rowok) {
            const float* rowp = xp + gr * HW + colL;
            if (ldL) {
                const float4 t = *reinterpret_cast<const float4*>(rowp);
                v[0] = t.x; v[1] = t.y; v[2] = t.z; v[3] = t.w;
            } else {
                v[0] = NEG_INF; v[1] = NEG_INF; v[2] = NEG_INF; v[3] = NEG_INF;
            }
            if (ldR) {
                const float4 t = *reinterpret_cast<const float4*>(rowp + 4);
                v[4] = t.x; v[5] = t.y; v[6] = t.z; v[7] = t.w;
            } else {
                v[4] = NEG_INF; v[5] = NEG_INF; v[6] = NEG_INF; v[7] = NEG_INF;
            }
        } else {
#pragma unroll
            for (int q = 0; q < 8; q++) v[q] = NEG_INF;
        }

        // Packed adjacent-value pairs vp[k] = (v[k], v[k+1]), k = 0..5.
        // Even k alias the float4 load register pairs; odd k cost 2 MOVs.
        u64 vp[6];
#pragma unroll
        for (int k = 0; k < 6; k++) vp[k] = pack2(v[k], v[k + 1]);

        // Output row oh = r begins accumulating at this input row.
        if (r < 8) {
            const int s = r % 5;
#pragma unroll
            for (int q = 0; q < 4; q++) acc[s][q] = NEG_INF;
        }

        // Input row r contributes to output rows oh = r - i, i = 0..4.
#pragma unroll
        for (int i = 0; i < 5; i++) {
            const int oh = r - i;
            if (oh >= 0 && oh < 8) {        // compile-time after unroll
                const int s = oh % 5;
#pragma unroll
                for (int q = 0; q < 4; q++) {
                    add2_max(acc[s][q], vp[q],     wp01[i]);   // taps j=0,1
                    add2_max(acc[s][q], vp[q + 2], wp23[i]);   // taps j=2,3
                    acc[s][q] = fmaxf(acc[s][q], v[q + 4] + w4[i]); // tap j=4
                }
            }
        }

        // Output row oh = r - 4 is complete after this input row: store it.
        if (r >= 4) {
            const int oh = r - 4;
            const int s  = oh % 5;
            float* orow  = op_base + oh * HW;
            if (tx > 0) {
                float2 t; t.x = acc[s][0]; t.y = acc[s][1];
                *reinterpret_cast<float2*>(orow) = t;
            }
            if (tx < 56) {
                float2 t; t.x = acc[s][2]; t.y = acc[s][3];
                *reinterpret_cast<float2*>(orow + 2) = t;
            }
        }
    }
}

extern "C" void kernel_launch(void* const* d_in, const int* in_sizes, int n_in,
                              void* d_out, int out_size)
{
    const float* x = (const float*)d_in[0];
    const float* w = (const float*)d_in[1];
    float* out     = (float*)d_out;
    // 256 planes * 28 row-groups * 57 col-groups = 408576 threads = 1596 blocks
    tropical_conv_kernel<<<1596, 256>>>(x, w, out);
}